// round 10
// baseline (speedup 1.0000x reference)
#include <cuda_runtime.h>
#include <cuda_bf16.h>

#define TLEN 2048
#define H 20
typedef unsigned long long ull;

// ---- packed f32x2 helpers ----
__device__ __forceinline__ ull pk(float lo, float hi) {
    ull r; asm("mov.b64 %0, {%1, %2};" : "=l"(r) : "f"(lo), "f"(hi)); return r;
}
__device__ __forceinline__ float2 upk(ull v) {
    float2 f; asm("mov.b64 {%0, %1}, %2;" : "=f"(f.x), "=f"(f.y) : "l"(v)); return f;
}
__device__ __forceinline__ ull fma2(ull a, ull b, ull c) {
    ull d; asm("fma.rn.f32x2 %0, %1, %2, %3;" : "=l"(d) : "l"(a), "l"(b), "l"(c)); return d;
}
__device__ __forceinline__ ull mul2(ull a, ull b) {
    ull d; asm("mul.rn.f32x2 %0, %1, %2;" : "=l"(d) : "l"(a), "l"(b)); return d;
}
__device__ __forceinline__ ull add2(ull a, ull b) {
    ull d; asm("add.rn.f32x2 %0, %1, %2;" : "=l"(d) : "l"(a), "l"(b)); return d;
}
// single-MUFU tanh; per-step err ~6e-4 contracts through the recurrence
// (R8 measured final rel_err 3.5e-7)
__device__ __forceinline__ float tanh_hw(float z) {
    float r; asm("tanh.approx.f32 %0, %1;" : "=f"(r) : "f"(z)); return r;
}
__device__ __forceinline__ float sigmoid1(float z) {
    float e; asm("ex2.approx.f32 %0, %1;" : "=f"(e) : "f"(z * -1.4426950408889634f));
    float r; asm("rcp.approx.f32 %0, %1;" : "=f"(r) : "f"(e + 1.0f));
    return r;
}

// K-pair permutation (dot order-free):
//   j in [0,8): (5*(j>>1) + 2*(j&1), +1) -> thread q OWNS pairs 2q, 2q+1
//   j = 8: rows (4,9)   j = 9: rows (14,19)  (straddle pairs)
__device__ __forceinline__ int pairA(int j) {
    if (j == 8) return 4;
    if (j == 9) return 14;
    return 5 * (j >> 1) + 2 * (j & 1);
}
__device__ __forceinline__ int pairB(int j) {
    if (j == 8) return 9;
    if (j == 9) return 19;
    return 5 * (j >> 1) + 2 * (j & 1) + 1;
}

// R9 = R7 exchange + R8 math, rebalanced for WARP COUNT:
// 1 stream/thread, 4 thr/batch -> 2048 warps (13.8/SM, 3.46/SMSP) for
// scheduler-level latency hiding (R8 showed 2-stream ILP at 1024 warps
// leaves issue at 46% -- both streams stall at the same sync points).
// Register budget engineered for 14 blocks/SM WITHOUT a cap (caps spill:
// R4/R6): weight pairs j=0..7 in registers (80 regs), pairs j=8,9 from
// warp-broadcast smem (one LDS.128/row, quad slots within 64B).
// Dot = two 5-deep fma2 chains + add2. tanh = MUFU.TANH.
__global__ void __launch_bounds__(32) rnn_kernel(
    const float* __restrict__ x,      // [B, TLEN]
    const float* __restrict__ W_ih,   // [H]
    const float* __restrict__ W_hh,   // [H, H]
    const float* __restrict__ b_ih,   // [H]
    const float* __restrict__ b_hh,   // [H]
    const float* __restrict__ W_fc,   // [H]
    const float* __restrict__ b_fc,   // [1]
    float* __restrict__ out)          // [B]
{
    __shared__ float sW[H][H];
    __shared__ __align__(16) ulonglong2 sTailW[5][4]; // [i][q] = pairs j=8,9 of row 5q+i
    __shared__ ull hbuf[2][10][8];                    // [buf][pair][batch8]
    __shared__ float sWih[H], sPre[H], sWfc[H];
    __shared__ float sBfc;

    const int tid = threadIdx.x;
    for (int i = tid; i < H * H; i += 32) sW[i / H][i % H] = W_hh[i];
    if (tid < H) {
        sWih[tid] = W_ih[tid];
        sPre[tid] = b_ih[tid] + b_hh[tid];
        sWfc[tid] = W_fc[tid];
    }
    if (tid == 0) sBfc = b_fc[0];
    __syncthreads();
    for (int idx = tid; idx < 5 * 4; idx += 32) {     // tail pairs j=8,9
        int qq = idx & 3, ii = idx >> 2;
        const float* row = sW[5 * qq + ii];
        ulonglong2 v;
        v.x = pk(row[4],  row[9]);    // pair j=8
        v.y = pk(row[14], row[19]);   // pair j=9
        sTailW[ii][qq] = v;
    }
    __syncthreads();

    const int q  = tid & 3;
    const int b8 = tid >> 2;
    const int batch = blockIdx.x * 8 + b8;

    // register weights: rows 5q..5q+4, pairs j=0..7 only (80 regs)
    ull wk[5][8], pre2[5];
    float wih[5];
    #pragma unroll
    for (int i = 0; i < 5; i++) {
        const int r = 5 * q + i;
        #pragma unroll
        for (int j = 0; j < 8; j++)
            wk[i][j] = pk(sW[r][pairA(j)], sW[r][pairB(j)]);
        wih[i]  = sWih[r];
        pre2[i] = pk(sPre[r], 0.0f);
    }

    ull hp[10];
    #pragma unroll
    for (int j = 0; j < 10; j++) hp[j] = 0ull;

    const float* xp = x + (size_t)batch * TLEN;

    for (int t = 0; t < TLEN; t += 4) {
        const float4 xv = *(const float4*)(xp + t);
        const float xs[4] = {xv.x, xv.y, xv.z, xv.w};

        #pragma unroll
        for (int s = 0; s < 4; s++) {
            const int buf = s & 1;
            float m[5];
            #pragma unroll
            for (int i = 0; i < 5; i++) {
                const ulonglong2 tw = sTailW[i][q];   // broadcast LDS.128
                // two independent 5-deep chains
                ull aL = fma2(wk[i][0], hp[0], pre2[i]);
                ull aH = mul2(wk[i][4], hp[4]);
                aL = fma2(wk[i][1], hp[1], aL);
                aH = fma2(wk[i][5], hp[5], aH);
                aL = fma2(wk[i][2], hp[2], aL);
                aH = fma2(wk[i][6], hp[6], aH);
                aL = fma2(wk[i][3], hp[3], aL);
                aH = fma2(wk[i][7], hp[7], aH);
                aL = fma2(tw.x,     hp[8], aL);
                aH = fma2(tw.y,     hp[9], aH);
                float2 f = upk(add2(aL, aH));
                m[i] = tanh_hw(fmaf(xs[s], wih[i], f.x + f.y));
            }
            // quad h-exchange: pairs land pre-packed, one syncwarp
            hbuf[buf][2 * q][b8]     = pk(m[0], m[1]);            // STS.64
            hbuf[buf][2 * q + 1][b8] = pk(m[2], m[3]);            // STS.64
            ((float*)&hbuf[buf][8 + (q >> 1)][b8])[q & 1] = m[4]; // STS.32
            __syncwarp();
            #pragma unroll
            for (int j = 0; j < 10; j++) hp[j] = hbuf[buf][j][b8]; // LDS.64
        }
    }

    if (q == 0) {
        ull acc = pk(sBfc, 0.0f);
        #pragma unroll
        for (int j = 0; j < 10; j++)
            acc = fma2(hp[j], pk(sWfc[pairA(j)], sWfc[pairB(j)]), acc);
        float2 f = upk(acc);
        out[batch] = sigmoid1(f.x + f.y);
    }
}

extern "C" void kernel_launch(void* const* d_in, const int* in_sizes, int n_in,
                              void* d_out, int out_size) {
    const float* x    = (const float*)d_in[0];
    const float* W_ih = (const float*)d_in[1];
    const float* W_hh = (const float*)d_in[2];
    const float* b_ih = (const float*)d_in[3];
    const float* b_hh = (const float*)d_in[4];
    const float* W_fc = (const float*)d_in[5];
    const float* b_fc = (const float*)d_in[6];
    float* out = (float*)d_out;

    const int B = in_sizes[0] / TLEN;   // 16384
    const int blocks = B / 8;           // 2048 blocks x 32 threads, 1 batch/thread-quad
    rnn_kernel<<<blocks, 32>>>(x, W_ih, W_hh, b_ih, b_hh, W_fc, b_fc, out);
}

// round 11
// speedup vs baseline: 1.1860x; 1.1860x over previous
#include <cuda_runtime.h>
#include <cuda_bf16.h>

#define TLEN 2048
#define H 20
typedef unsigned long long ull;

// ---- packed f32x2 helpers ----
__device__ __forceinline__ ull pk(float lo, float hi) {
    ull r; asm("mov.b64 %0, {%1, %2};" : "=l"(r) : "f"(lo), "f"(hi)); return r;
}
__device__ __forceinline__ float2 upk(ull v) {
    float2 f; asm("mov.b64 {%0, %1}, %2;" : "=f"(f.x), "=f"(f.y) : "l"(v)); return f;
}
__device__ __forceinline__ ull fma2(ull a, ull b, ull c) {
    ull d; asm("fma.rn.f32x2 %0, %1, %2, %3;" : "=l"(d) : "l"(a), "l"(b), "l"(c)); return d;
}
__device__ __forceinline__ ull mul2(ull a, ull b) {
    ull d; asm("mul.rn.f32x2 %0, %1, %2;" : "=l"(d) : "l"(a), "l"(b)); return d;
}
__device__ __forceinline__ ull add2(ull a, ull b) {
    ull d; asm("add.rn.f32x2 %0, %1, %2;" : "=l"(d) : "l"(a), "l"(b)); return d;
}
__device__ __forceinline__ float tanh_hw(float z) {
    float r; asm("tanh.approx.f32 %0, %1;" : "=f"(r) : "f"(z)); return r;
}
__device__ __forceinline__ float sigmoid1(float z) {
    float e; asm("ex2.approx.f32 %0, %1;" : "=f"(e) : "f"(z * -1.4426950408889634f));
    float r; asm("rcp.approx.f32 %0, %1;" : "=f"(r) : "f"(e + 1.0f));
    return r;
}

// K-pair permutation (dot order-free):
//   j in [0,8): (5*(j>>1) + 2*(j&1), +1) -> thread q OWNS pairs 2q, 2q+1
//   j = 8: rows (4,9)   j = 9: rows (14,19)
__device__ __forceinline__ int pairA(int j) {
    if (j == 8) return 4;
    if (j == 9) return 14;
    return 5 * (j >> 1) + 2 * (j & 1);
}
__device__ __forceinline__ int pairB(int j) {
    if (j == 8) return 9;
    if (j == 9) return 19;
    return 5 * (j >> 1) + 2 * (j & 1) + 1;
}

// ============ LEAN 1-stream kernel: 2048 warps, engineered <=146 regs =======
// Input projection folded into the dot chain as a virtual K-pair:
// (wih_r, pre_r) . (x, 1) -- removes pre2[]/wih[] regs and the per-row fmaf.
// Weight pairs j=0..7 in regs (80), j=8,9 via broadcast LDS.128.
__global__ void __launch_bounds__(32) rnn_lean(
    const float* __restrict__ x, const float* __restrict__ W_ih,
    const float* __restrict__ W_hh, const float* __restrict__ b_ih,
    const float* __restrict__ b_hh, const float* __restrict__ W_fc,
    const float* __restrict__ b_fc, float* __restrict__ out)
{
    __shared__ float sW[H][H];
    __shared__ __align__(16) ulonglong2 sTailW[5][4];  // [i][q] = pairs j=8,9
    __shared__ ull hbuf[2][10][8];
    __shared__ float sWih[H], sPre[H], sWfc[H];
    __shared__ float sBfc;

    const int tid = threadIdx.x;
    for (int i = tid; i < H * H; i += 32) sW[i / H][i % H] = W_hh[i];
    if (tid < H) {
        sWih[tid] = W_ih[tid];
        sPre[tid] = b_ih[tid] + b_hh[tid];
        sWfc[tid] = W_fc[tid];
    }
    if (tid == 0) sBfc = b_fc[0];
    __syncthreads();
    for (int idx = tid; idx < 5 * 4; idx += 32) {
        int qq = idx & 3, ii = idx >> 2;
        const float* row = sW[5 * qq + ii];
        ulonglong2 v;
        v.x = pk(row[4],  row[9]);
        v.y = pk(row[14], row[19]);
        sTailW[ii][qq] = v;
    }
    __syncthreads();

    const int q  = tid & 3;
    const int b8 = tid >> 2;
    const int batch = blockIdx.x * 8 + b8;

    ull wk[5][8], wihpre[5];
    #pragma unroll
    for (int i = 0; i < 5; i++) {
        const int r = 5 * q + i;
        #pragma unroll
        for (int j = 0; j < 8; j++)
            wk[i][j] = pk(sW[r][pairA(j)], sW[r][pairB(j)]);
        wihpre[i] = pk(sWih[r], sPre[r]);
    }

    ull hp[10];
    #pragma unroll
    for (int j = 0; j < 10; j++) hp[j] = 0ull;

    const float* xp = x + (size_t)batch * TLEN;

    for (int t = 0; t < TLEN; t += 4) {
        const float4 xv = *(const float4*)(xp + t);
        const float xs[4] = {xv.x, xv.y, xv.z, xv.w};

        #pragma unroll
        for (int s = 0; s < 4; s++) {
            const int buf = s & 1;
            const ull hx = pk(xs[s], 1.0f);   // virtual pair (x, 1)
            float m[5];
            #pragma unroll
            for (int i = 0; i < 5; i++) {
                const ulonglong2 tw = sTailW[i][q];   // broadcast LDS.128
                ull aL = mul2(wk[i][0], hp[0]);       // chain L: j=0..4
                ull aH = mul2(wihpre[i], hx);         // chain H: proj + j=5..9
                aL = fma2(wk[i][1], hp[1], aL);
                aH = fma2(wk[i][5], hp[5], aH);
                aL = fma2(wk[i][2], hp[2], aL);
                aH = fma2(wk[i][6], hp[6], aH);
                aL = fma2(wk[i][3], hp[3], aL);
                aH = fma2(wk[i][7], hp[7], aH);
                aL = fma2(wk[i][4], hp[4], aL);
                aH = fma2(tw.x,     hp[8], aH);
                aH = fma2(tw.y,     hp[9], aH);
                float2 f = upk(add2(aL, aH));
                m[i] = tanh_hw(f.x + f.y);
            }
            hbuf[buf][2 * q][b8]     = pk(m[0], m[1]);
            hbuf[buf][2 * q + 1][b8] = pk(m[2], m[3]);
            ((float*)&hbuf[buf][8 + (q >> 1)][b8])[q & 1] = m[4];
            __syncwarp();
            #pragma unroll
            for (int j = 0; j < 10; j++) hp[j] = hbuf[buf][j][b8];
        }
    }

    if (q == 0) {
        ull acc = pk(sBfc, 0.0f);
        #pragma unroll
        for (int j = 0; j < 10; j++)
            acc = fma2(hp[j], pk(sWfc[pairA(j)], sWfc[pairB(j)]), acc);
        float2 f = upk(acc);
        out[batch] = sigmoid1(f.x + f.y);
    }
}

// ============ FALLBACK: R8 verbatim (proven 811 us) =========================
__global__ void __launch_bounds__(32) rnn_r8(
    const float* __restrict__ x, const float* __restrict__ W_ih,
    const float* __restrict__ W_hh, const float* __restrict__ b_ih,
    const float* __restrict__ b_hh, const float* __restrict__ W_fc,
    const float* __restrict__ b_fc, float* __restrict__ out)
{
    __shared__ float sW[H][H];
    __shared__ ull hbuf[2][2][10][8];
    __shared__ float sWih[H], sPre[H], sWfc[H];
    __shared__ float sBfc;

    const int tid = threadIdx.x;
    for (int i = tid; i < H * H; i += 32) sW[i / H][i % H] = W_hh[i];
    if (tid < H) {
        sWih[tid] = W_ih[tid];
        sPre[tid] = b_ih[tid] + b_hh[tid];
        sWfc[tid] = W_fc[tid];
    }
    if (tid == 0) sBfc = b_fc[0];
    __syncthreads();

    const int q  = tid & 3;
    const int b8 = tid >> 2;
    const int batchA = blockIdx.x * 16 + b8;
    const int batchB = batchA + 8;

    ull wk[5][10], pre2[5];
    float wih[5];
    #pragma unroll
    for (int i = 0; i < 5; i++) {
        const int r = 5 * q + i;
        #pragma unroll
        for (int j = 0; j < 10; j++)
            wk[i][j] = pk(sW[r][pairA(j)], sW[r][pairB(j)]);
        wih[i]  = sWih[r];
        pre2[i] = pk(sPre[r], 0.0f);
    }

    ull ha[10], hb[10];
    #pragma unroll
    for (int j = 0; j < 10; j++) { ha[j] = 0ull; hb[j] = 0ull; }

    const float* xpA = x + (size_t)batchA * TLEN;
    const float* xpB = x + (size_t)batchB * TLEN;

    for (int t = 0; t < TLEN; t += 4) {
        const float4 xva = *(const float4*)(xpA + t);
        const float4 xvb = *(const float4*)(xpB + t);
        const float xa[4] = {xva.x, xva.y, xva.z, xva.w};
        const float xb[4] = {xvb.x, xvb.y, xvb.z, xvb.w};

        #pragma unroll
        for (int s = 0; s < 4; s++) {
            const int buf = s & 1;
            float ma[5], mb[5];
            #pragma unroll
            for (int i = 0; i < 5; i++) {
                ull aL = fma2(wk[i][0], ha[0], pre2[i]);
                ull aH = mul2(wk[i][5], ha[5]);
                ull bL = fma2(wk[i][0], hb[0], pre2[i]);
                ull bH = mul2(wk[i][5], hb[5]);
                #pragma unroll
                for (int j = 1; j < 5; j++) {
                    aL = fma2(wk[i][j], ha[j], aL);
                    aH = fma2(wk[i][5 + j], ha[5 + j], aH);
                    bL = fma2(wk[i][j], hb[j], bL);
                    bH = fma2(wk[i][5 + j], hb[5 + j], bH);
                }
                float2 fa = upk(add2(aL, aH));
                float2 fb = upk(add2(bL, bH));
                ma[i] = tanh_hw(fmaf(xa[s], wih[i], fa.x + fa.y));
                mb[i] = tanh_hw(fmaf(xb[s], wih[i], fb.x + fb.y));
            }
            hbuf[buf][0][2 * q][b8]     = pk(ma[0], ma[1]);
            hbuf[buf][0][2 * q + 1][b8] = pk(ma[2], ma[3]);
            ((float*)&hbuf[buf][0][8 + (q >> 1)][b8])[q & 1] = ma[4];
            hbuf[buf][1][2 * q][b8]     = pk(mb[0], mb[1]);
            hbuf[buf][1][2 * q + 1][b8] = pk(mb[2], mb[3]);
            ((float*)&hbuf[buf][1][8 + (q >> 1)][b8])[q & 1] = mb[4];
            __syncwarp();
            #pragma unroll
            for (int j = 0; j < 10; j++) {
                ha[j] = hbuf[buf][0][j][b8];
                hb[j] = hbuf[buf][1][j][b8];
            }
        }
    }

    if (q == 0) {
        ull accA = pk(sBfc, 0.0f), accB = pk(sBfc, 0.0f);
        #pragma unroll
        for (int j = 0; j < 10; j++) {
            ull wf = pk(sWfc[pairA(j)], sWfc[pairB(j)]);
            accA = fma2(ha[j], wf, accA);
            accB = fma2(hb[j], wf, accB);
        }
        float2 fa = upk(accA), fb = upk(accB);
        out[batchA] = sigmoid1(fa.x + fa.y);
        out[batchB] = sigmoid1(fb.x + fb.y);
    }
}

extern "C" void kernel_launch(void* const* d_in, const int* in_sizes, int n_in,
                              void* d_out, int out_size) {
    const float* x    = (const float*)d_in[0];
    const float* W_ih = (const float*)d_in[1];
    const float* W_hh = (const float*)d_in[2];
    const float* b_ih = (const float*)d_in[3];
    const float* b_hh = (const float*)d_in[4];
    const float* W_fc = (const float*)d_in[5];
    const float* b_fc = (const float*)d_in[6];
    float* out = (float*)d_out;

    const int B = in_sizes[0] / TLEN;   // 16384

    // Deterministic launch-time hedge: lean kernel needs <=146 regs for
    // 14 blocks/SM (single wave at 2048 blocks). If ptxas exceeded that,
    // a 2-wave run would cost ~+30% (R7/R9) -> use the proven R8 kernel.
    cudaFuncAttributes attr;
    cudaFuncGetAttributes(&attr, rnn_lean);
    if (attr.numRegs <= 146) {
        rnn_lean<<<B / 8, 32>>>(x, W_ih, W_hh, b_ih, b_hh, W_fc, b_fc, out);
    } else {
        rnn_r8<<<B / 16, 32>>>(x, W_ih, W_hh, b_ih, b_hh, W_fc, b_fc, out);
    }
}